// round 1
// baseline (speedup 1.0000x reference)
#include <cuda_runtime.h>
#include <math.h>

// Problem constants
#define Bn 4
#define Sn 2048
#define Dn 2048
#define Hn 16
#define DHn 128
#define TDn 6144            // 3*D
#define NROWS (Bn*Sn)       // 8192

// Scratch (device globals; no cudaMalloc allowed)
__device__ float g_qkv[(size_t)NROWS * TDn];   // 201 MB
__device__ float g_y[(size_t)NROWS * Dn];      // 67 MB

// ---------------------------------------------------------------------------
// SGEMM: C[M,N] = A[M,K] @ W[N,K]^T + bias[N]
// 128x128 tile, BK=8, 8x8 per thread, 256 threads
// ---------------------------------------------------------------------------
__global__ __launch_bounds__(256) void sgemm_bias_kernel(
    const float* __restrict__ A, const float* __restrict__ W,
    const float* __restrict__ bias, float* __restrict__ C,
    int M, int N, int K)
{
    __shared__ float As[8][128];
    __shared__ float Bs[8][128];

    const int tid = threadIdx.x;
    const int tx = tid & 15;       // 0..15 (N dir)
    const int ty = tid >> 4;       // 0..15 (M dir)
    const int m0 = blockIdx.y << 7;
    const int n0 = blockIdx.x << 7;

    const int lr = tid >> 1;             // 0..127 row within tile
    const int lc = (tid & 1) << 2;       // 0 or 4

    const float* Ap = A + (size_t)(m0 + lr) * K + lc;
    const float* Wp = W + (size_t)(n0 + lr) * K + lc;

    float acc[8][8];
#pragma unroll
    for (int i = 0; i < 8; i++)
#pragma unroll
        for (int j = 0; j < 8; j++) acc[i][j] = 0.f;

    for (int k0 = 0; k0 < K; k0 += 8) {
        float4 a4 = *(const float4*)(Ap + k0);
        float4 b4 = *(const float4*)(Wp + k0);
        As[lc + 0][lr] = a4.x; As[lc + 1][lr] = a4.y;
        As[lc + 2][lr] = a4.z; As[lc + 3][lr] = a4.w;
        Bs[lc + 0][lr] = b4.x; Bs[lc + 1][lr] = b4.y;
        Bs[lc + 2][lr] = b4.z; Bs[lc + 3][lr] = b4.w;
        __syncthreads();

#pragma unroll
        for (int k = 0; k < 8; k++) {
            float ra[8], rb[8];
            *(float4*)(ra)     = *(const float4*)&As[k][ty * 8];
            *(float4*)(ra + 4) = *(const float4*)&As[k][ty * 8 + 4];
            *(float4*)(rb)     = *(const float4*)&Bs[k][tx * 8];
            *(float4*)(rb + 4) = *(const float4*)&Bs[k][tx * 8 + 4];
#pragma unroll
            for (int i = 0; i < 8; i++)
#pragma unroll
                for (int j = 0; j < 8; j++)
                    acc[i][j] = fmaf(ra[i], rb[j], acc[i][j]);
        }
        __syncthreads();
    }

    const float* bp = bias + n0 + tx * 8;
    float bj[8];
#pragma unroll
    for (int j = 0; j < 8; j++) bj[j] = bp[j];

#pragma unroll
    for (int i = 0; i < 8; i++) {
        float* Crow = C + (size_t)(m0 + ty * 8 + i) * N + n0 + tx * 8;
        float4 o0, o1;
        o0.x = acc[i][0] + bj[0]; o0.y = acc[i][1] + bj[1];
        o0.z = acc[i][2] + bj[2]; o0.w = acc[i][3] + bj[3];
        o1.x = acc[i][4] + bj[4]; o1.y = acc[i][5] + bj[5];
        o1.z = acc[i][6] + bj[6]; o1.w = acc[i][7] + bj[7];
        *(float4*)(Crow) = o0;
        *(float4*)(Crow + 4) = o1;
    }
}

// ---------------------------------------------------------------------------
// RoPE applied in-place to q and k halves of g_qkv
// one thread per (b,s,h,d2) pair; d2 in [0,64)
// ---------------------------------------------------------------------------
__global__ __launch_bounds__(256) void rope_kernel(float* __restrict__ qkv)
{
    int idx = blockIdx.x * blockDim.x + threadIdx.x;
    const int total = Bn * Sn * Hn * (DHn / 2);
    if (idx >= total) return;

    int d2 = idx & 63;
    int h  = (idx >> 6) & 15;
    int bs = idx >> 10;            // 0..8191
    int s  = bs & (Sn - 1);

    float freq  = powf(10000.0f, -(float)d2 / 64.0f);
    float angle = (float)s * freq;
    float sn, cs;
    sincosf(angle, &sn, &cs);

    size_t base = (size_t)bs * TDn + h * DHn + 2 * d2;

    // q
    float x1 = qkv[base], x2 = qkv[base + 1];
    qkv[base]     = x1 * cs - x2 * sn;
    qkv[base + 1] = x1 * sn + x2 * cs;
    // k (offset +D)
    float y1 = qkv[base + Dn], y2 = qkv[base + Dn + 1];
    qkv[base + Dn]     = y1 * cs - y2 * sn;
    qkv[base + Dn + 1] = y1 * sn + y2 * cs;
}

// ---------------------------------------------------------------------------
// Flash attention (causal), fp32. 64 q-rows x 64 k-rows tile, dh=128.
// grid: (S/64, B*H), 256 threads. dynamic smem.
// ---------------------------------------------------------------------------
#define QSTR 129
#define VSTR 132
#define PSTR 65

__global__ __launch_bounds__(256) void flash_attn_kernel(
    const float* __restrict__ qkv, float* __restrict__ Y)
{
    extern __shared__ float sm[];
    float* Qs    = sm;                      // 64*129
    float* Ks    = Qs + 64 * QSTR;          // 64*129
    float* Vs    = Ks + 64 * QSTR;          // 64*132
    float* Ps    = Vs + 64 * VSTR;          // 64*65
    float* row_m = Ps + 64 * PSTR;          // 64
    float* row_l = row_m + 64;              // 64
    float* row_a = row_l + 64;              // 64

    const int tid = threadIdx.x;
    const int tx = tid & 15;
    const int ty = tid >> 4;
    const int bh = blockIdx.y;
    const int b = bh >> 4;
    const int h = bh & 15;
    const int qb = blockIdx.x;
    const int q0 = qb * 64;

    const float* qbase = qkv + ((size_t)(b * Sn + q0)) * TDn + h * DHn;
    const float* kbase = qkv + ((size_t)(b * Sn)) * TDn + Dn + h * DHn;
    const float* vbase = kbase + Dn;

    // Load Q tile
    for (int idx = tid; idx < 64 * 32; idx += 256) {
        int r = idx >> 5, c4 = (idx & 31) * 4;
        float4 v = *(const float4*)(qbase + (size_t)r * TDn + c4);
        float* dst = &Qs[r * QSTR + c4];
        dst[0] = v.x; dst[1] = v.y; dst[2] = v.z; dst[3] = v.w;
    }
    if (tid < 64) { row_m[tid] = -1e30f; row_l[tid] = 0.f; }

    float o[4][8];
#pragma unroll
    for (int i = 0; i < 4; i++)
#pragma unroll
        for (int c = 0; c < 8; c++) o[i][c] = 0.f;

    const float scale = 0.08838834764831845f; // 1/sqrt(128)

    for (int kb = 0; kb <= qb; kb++) {
        __syncthreads();   // protect Ks/Vs/Ps from previous iter readers
        const int k0 = kb * 64;
        // Load K,V tiles
        for (int idx = tid; idx < 64 * 32; idx += 256) {
            int r = idx >> 5, c4 = (idx & 31) * 4;
            const size_t goff = (size_t)(k0 + r) * TDn + c4;
            float4 kv = *(const float4*)(kbase + goff);
            float* kd = &Ks[r * QSTR + c4];
            kd[0] = kv.x; kd[1] = kv.y; kd[2] = kv.z; kd[3] = kv.w;
            float4 vv = *(const float4*)(vbase + goff);
            *(float4*)&Vs[r * VSTR + c4] = vv;
        }
        __syncthreads();

        // S = scale * Q K^T  (4x4 per thread)
        float s[4][4];
#pragma unroll
        for (int i = 0; i < 4; i++)
#pragma unroll
            for (int j = 0; j < 4; j++) s[i][j] = 0.f;

        const float* q0p = &Qs[(ty * 4 + 0) * QSTR];
        const float* q1p = &Qs[(ty * 4 + 1) * QSTR];
        const float* q2p = &Qs[(ty * 4 + 2) * QSTR];
        const float* q3p = &Qs[(ty * 4 + 3) * QSTR];
        const float* k0p = &Ks[(tx * 4 + 0) * QSTR];
        const float* k1p = &Ks[(tx * 4 + 1) * QSTR];
        const float* k2p = &Ks[(tx * 4 + 2) * QSTR];
        const float* k3p = &Ks[(tx * 4 + 3) * QSTR];

#pragma unroll 4
        for (int d = 0; d < DHn; d++) {
            float qv[4], kv[4];
            qv[0] = q0p[d]; qv[1] = q1p[d]; qv[2] = q2p[d]; qv[3] = q3p[d];
            kv[0] = k0p[d]; kv[1] = k1p[d]; kv[2] = k2p[d]; kv[3] = k3p[d];
#pragma unroll
            for (int i = 0; i < 4; i++)
#pragma unroll
                for (int j = 0; j < 4; j++)
                    s[i][j] = fmaf(qv[i], kv[j], s[i][j]);
        }

        const bool diag = (kb == qb);
#pragma unroll
        for (int i = 0; i < 4; i++) {
#pragma unroll
            for (int j = 0; j < 4; j++) {
                float val = s[i][j] * scale;
                if (diag && (tx * 4 + j > ty * 4 + i)) val = -1e30f;
                Ps[(ty * 4 + i) * PSTR + tx * 4 + j] = val;
            }
        }
        __syncthreads();

        // Row stats: 4 threads per row
        {
            const int r = tid >> 2, part = tid & 3;
            float* prow = &Ps[r * PSTR + part * 16];
            float mx = -1e30f;
#pragma unroll
            for (int j = 0; j < 16; j++) mx = fmaxf(mx, prow[j]);
            mx = fmaxf(mx, __shfl_xor_sync(0xffffffffu, mx, 1));
            mx = fmaxf(mx, __shfl_xor_sync(0xffffffffu, mx, 2));
            const float m_old = row_m[r];
            const float m_new = fmaxf(m_old, mx);
            float sum = 0.f;
#pragma unroll
            for (int j = 0; j < 16; j++) {
                float p = __expf(prow[j] - m_new);
                prow[j] = p;
                sum += p;
            }
            sum += __shfl_xor_sync(0xffffffffu, sum, 1);
            sum += __shfl_xor_sync(0xffffffffu, sum, 2);
            if (part == 0) {
                float alpha = __expf(m_old - m_new);
                row_l[r] = row_l[r] * alpha + sum;
                row_m[r] = m_new;
                row_a[r] = alpha;
            }
        }
        __syncthreads();

        // O = O*alpha + P @ V
        float al[4];
#pragma unroll
        for (int i = 0; i < 4; i++) al[i] = row_a[ty * 4 + i];
#pragma unroll
        for (int i = 0; i < 4; i++)
#pragma unroll
            for (int c = 0; c < 8; c++) o[i][c] *= al[i];

#pragma unroll 2
        for (int j = 0; j < 64; j++) {
            float p[4];
#pragma unroll
            for (int i = 0; i < 4; i++) p[i] = Ps[(ty * 4 + i) * PSTR + j];
            float4 v0 = *(const float4*)&Vs[j * VSTR + tx * 8];
            float4 v1 = *(const float4*)&Vs[j * VSTR + tx * 8 + 4];
#pragma unroll
            for (int i = 0; i < 4; i++) {
                o[i][0] = fmaf(p[i], v0.x, o[i][0]);
                o[i][1] = fmaf(p[i], v0.y, o[i][1]);
                o[i][2] = fmaf(p[i], v0.z, o[i][2]);
                o[i][3] = fmaf(p[i], v0.w, o[i][3]);
                o[i][4] = fmaf(p[i], v1.x, o[i][4]);
                o[i][5] = fmaf(p[i], v1.y, o[i][5]);
                o[i][6] = fmaf(p[i], v1.z, o[i][6]);
                o[i][7] = fmaf(p[i], v1.w, o[i][7]);
            }
        }
    }

    // Write normalized output
#pragma unroll
    for (int i = 0; i < 4; i++) {
        const int r = ty * 4 + i;
        const float inv = 1.0f / row_l[r];
        float* yp = Y + ((size_t)(b * Sn + q0 + r)) * Dn + h * DHn + tx * 8;
        float4 o0, o1;
        o0.x = o[i][0] * inv; o0.y = o[i][1] * inv;
        o0.z = o[i][2] * inv; o0.w = o[i][3] * inv;
        o1.x = o[i][4] * inv; o1.y = o[i][5] * inv;
        o1.z = o[i][6] * inv; o1.w = o[i][7] * inv;
        *(float4*)(yp) = o0;
        *(float4*)(yp + 4) = o1;
    }
}

// ---------------------------------------------------------------------------
extern "C" void kernel_launch(void* const* d_in, const int* in_sizes, int n_in,
                              void* d_out, int out_size)
{
    (void)in_sizes; (void)n_in; (void)out_size;
    const float* x      = (const float*)d_in[0];
    const float* qkv_w  = (const float*)d_in[1];
    const float* qkv_b  = (const float*)d_in[2];
    const float* out_w  = (const float*)d_in[3];
    const float* out_b  = (const float*)d_in[4];
    float* out = (float*)d_out;

    float *qkv, *y;
    cudaGetSymbolAddress((void**)&qkv, g_qkv);
    cudaGetSymbolAddress((void**)&y, g_y);

    // 1) QKV projection: [8192,2048] @ [6144,2048]^T
    {
        dim3 grid(TDn / 128, NROWS / 128);
        sgemm_bias_kernel<<<grid, 256>>>(x, qkv_w, qkv_b, qkv, NROWS, TDn, Dn);
    }

    // 2) RoPE on q,k
    {
        int total = Bn * Sn * Hn * (DHn / 2);
        rope_kernel<<<(total + 255) / 256, 256>>>(qkv);
    }

    // 3) Flash attention
    {
        const int smem_bytes = (64 * QSTR * 2 + 64 * VSTR + 64 * PSTR + 3 * 64) * sizeof(float);
        cudaFuncSetAttribute(flash_attn_kernel,
                             cudaFuncAttributeMaxDynamicSharedMemorySize, smem_bytes);
        dim3 grid(Sn / 64, Bn * Hn);
        flash_attn_kernel<<<grid, 256, smem_bytes>>>(qkv, y);
    }

    // 4) Output projection: [8192,2048] @ [2048,2048]^T
    {
        dim3 grid(Dn / 128, NROWS / 128);
        sgemm_bias_kernel<<<grid, 256>>>(y, out_w, out_b, out, NROWS, Dn, Dn);
    }
}

// round 3
// speedup vs baseline: 1.7399x; 1.7399x over previous
#include <cuda_runtime.h>
#include <cstdint>
#include <math.h>

// Problem constants
#define Bn 4
#define Sn 2048
#define Dn 2048
#define Hn 16
#define DHn 128
#define TDn 6144            // 3*D
#define NROWS (Bn*Sn)       // 8192

// Scratch (device globals; no cudaMalloc allowed)
__device__ float g_qkv[(size_t)NROWS * TDn];   // 201 MB
__device__ float g_y[(size_t)NROWS * Dn];      // 67 MB

// ---------------------------------------------------------------------------
// mma.sync tf32 GEMM: C[M,N] = A[M,K] @ W[N,K]^T + bias[N]
// CTA: 128x128 tile, 256 threads = 8 warps (2 m x 4 n), warp tile 64x32.
// K-chunk 32, double-buffered smem, padded stride 36 floats (conflict-free).
// ---------------------------------------------------------------------------
#define KC 32
#define ASTR 36
#define TILE_F (128 * ASTR)                 // floats per tile
#define GEMM_SMEM (4 * TILE_F * 4)          // 73728 bytes

__device__ __forceinline__ uint32_t f2tf32(float x) {
    uint32_t r;
    asm("cvt.rna.tf32.f32 %0, %1;" : "=r"(r) : "f"(x));
    return r;
}

__device__ __forceinline__ void mma_tf32(float* d,
                                         uint32_t a0, uint32_t a1,
                                         uint32_t a2, uint32_t a3,
                                         uint32_t b0, uint32_t b1) {
    asm volatile(
        "mma.sync.aligned.m16n8k8.row.col.f32.tf32.tf32.f32 "
        "{%0,%1,%2,%3}, {%4,%5,%6,%7}, {%8,%9}, {%0,%1,%2,%3};"
        : "+f"(d[0]), "+f"(d[1]), "+f"(d[2]), "+f"(d[3])
        : "r"(a0), "r"(a1), "r"(a2), "r"(a3), "r"(b0), "r"(b1));
}

__global__ __launch_bounds__(256) void mma_gemm_bias(
    const float* __restrict__ A, const float* __restrict__ W,
    const float* __restrict__ bias, float* __restrict__ C,
    int M, int N, int K)
{
    extern __shared__ float sm[];
    const int tid = threadIdx.x;
    const int wid = tid >> 5;
    const int lid = tid & 31;
    const int g   = lid >> 2;       // group id 0..7
    const int tg  = lid & 3;        // thread-in-group 0..3
    const int wm  = wid >> 2;       // 0..1  (warp m)
    const int wn  = wid & 3;        // 0..3  (warp n)
    const int m0 = blockIdx.y << 7;
    const int n0 = blockIdx.x << 7;

    // smem layout (floats): [A buf0][A buf1][B buf0][B buf1]
    float* Abuf[2] = { sm,              sm + TILE_F };
    float* Bbuf[2] = { sm + 2 * TILE_F, sm + 3 * TILE_F };

    const float* Abase = A + (size_t)m0 * K;
    const float* Wbase = W + (size_t)n0 * K;

    float acc[4][4][4];
#pragma unroll
    for (int mi = 0; mi < 4; mi++)
#pragma unroll
        for (int ni = 0; ni < 4; ni++)
#pragma unroll
            for (int r = 0; r < 4; r++) acc[mi][ni][r] = 0.f;

    const int nc = K / KC;

    // per-thread load mapping: 4 float4 per tile (A and B)
    float4 ra[4], rb[4];

    auto load_regs = [&](int c) {
        const int k0 = c * KC;
#pragma unroll
        for (int i = 0; i < 4; i++) {
            int idx = i * 256 + tid;
            int r  = idx >> 3;
            int c4 = (idx & 7) << 2;
            ra[i] = *(const float4*)(Abase + (size_t)r * K + k0 + c4);
            rb[i] = *(const float4*)(Wbase + (size_t)r * K + k0 + c4);
        }
    };

    auto sts_regs = [&](int buf) {
#pragma unroll
        for (int i = 0; i < 4; i++) {
            int idx = i * 256 + tid;
            int r  = idx >> 3;
            int c4 = (idx & 7) << 2;
            uint4 av = make_uint4(f2tf32(ra[i].x), f2tf32(ra[i].y),
                                  f2tf32(ra[i].z), f2tf32(ra[i].w));
            uint4 bv = make_uint4(f2tf32(rb[i].x), f2tf32(rb[i].y),
                                  f2tf32(rb[i].z), f2tf32(rb[i].w));
            *(uint4*)&Abuf[buf][r * ASTR + c4] = av;
            *(uint4*)&Bbuf[buf][r * ASTR + c4] = bv;
        }
    };

    auto mma_chunk = [&](int buf) {
        const float* As = Abuf[buf];
        const float* Bs = Bbuf[buf];
#pragma unroll
        for (int ks = 0; ks < 4; ks++) {
            const int kc = ks * 8;
            uint32_t af[4][4], bf[4][2];
#pragma unroll
            for (int mi = 0; mi < 4; mi++) {
                const float* ap = &As[(wm * 64 + mi * 16 + g) * ASTR + kc + tg];
                af[mi][0] = __float_as_uint(ap[0]);
                af[mi][1] = __float_as_uint(ap[8 * ASTR]);
                af[mi][2] = __float_as_uint(ap[4]);
                af[mi][3] = __float_as_uint(ap[8 * ASTR + 4]);
            }
#pragma unroll
            for (int ni = 0; ni < 4; ni++) {
                const float* bp = &Bs[(wn * 32 + ni * 8 + g) * ASTR + kc + tg];
                bf[ni][0] = __float_as_uint(bp[0]);
                bf[ni][1] = __float_as_uint(bp[4]);
            }
#pragma unroll
            for (int mi = 0; mi < 4; mi++)
#pragma unroll
                for (int ni = 0; ni < 4; ni++)
                    mma_tf32(acc[mi][ni],
                             af[mi][0], af[mi][1], af[mi][2], af[mi][3],
                             bf[ni][0], bf[ni][1]);
        }
    };

    // software pipeline
    load_regs(0);
    sts_regs(0);
    __syncthreads();

    for (int c = 0; c < nc; c++) {
        if (c + 1 < nc) load_regs(c + 1);
        mma_chunk(c & 1);
        __syncthreads();
        if (c + 1 < nc) {
            sts_regs((c + 1) & 1);
            __syncthreads();
        }
    }

    // epilogue: write C + bias
#pragma unroll
    for (int ni = 0; ni < 4; ni++) {
        const int col = n0 + wn * 32 + ni * 8 + 2 * tg;
        const float2 bj = *(const float2*)&bias[col];
#pragma unroll
        for (int mi = 0; mi < 4; mi++) {
            const int row = m0 + wm * 64 + mi * 16 + g;
            float2 o0, o1;
            o0.x = acc[mi][ni][0] + bj.x;
            o0.y = acc[mi][ni][1] + bj.y;
            o1.x = acc[mi][ni][2] + bj.x;
            o1.y = acc[mi][ni][3] + bj.y;
            *(float2*)&C[(size_t)row * N + col] = o0;
            *(float2*)&C[(size_t)(row + 8) * N + col] = o1;
        }
    }
}

// ---------------------------------------------------------------------------
// RoPE applied in-place to q and k halves of g_qkv
// ---------------------------------------------------------------------------
__global__ __launch_bounds__(256) void rope_kernel(float* __restrict__ qkv)
{
    int idx = blockIdx.x * blockDim.x + threadIdx.x;
    const int total = Bn * Sn * Hn * (DHn / 2);
    if (idx >= total) return;

    int d2 = idx & 63;
    int h  = (idx >> 6) & 15;
    int bs = idx >> 10;
    int s  = bs & (Sn - 1);

    float freq  = powf(10000.0f, -(float)d2 / 64.0f);
    float angle = (float)s * freq;
    float sn, cs;
    sincosf(angle, &sn, &cs);

    size_t base = (size_t)bs * TDn + h * DHn + 2 * d2;

    float x1 = qkv[base], x2 = qkv[base + 1];
    qkv[base]     = x1 * cs - x2 * sn;
    qkv[base + 1] = x1 * sn + x2 * cs;
    float y1 = qkv[base + Dn], y2 = qkv[base + Dn + 1];
    qkv[base + Dn]     = y1 * cs - y2 * sn;
    qkv[base + Dn + 1] = y1 * sn + y2 * cs;
}

// ---------------------------------------------------------------------------
// Flash attention (causal), fp32 SIMT. 64x64 tile, dh=128. (unchanged R1)
// ---------------------------------------------------------------------------
#define QSTR 129
#define VSTR 132
#define PSTR 65

__global__ __launch_bounds__(256) void flash_attn_kernel(
    const float* __restrict__ qkv, float* __restrict__ Y)
{
    extern __shared__ float smf[];
    float* Qs    = smf;
    float* Ks    = Qs + 64 * QSTR;
    float* Vs    = Ks + 64 * QSTR;
    float* Ps    = Vs + 64 * VSTR;
    float* row_m = Ps + 64 * PSTR;
    float* row_l = row_m + 64;
    float* row_a = row_l + 64;

    const int tid = threadIdx.x;
    const int tx = tid & 15;
    const int ty = tid >> 4;
    const int bh = blockIdx.y;
    const int b = bh >> 4;
    const int h = bh & 15;
    const int qb = blockIdx.x;
    const int q0 = qb * 64;

    const float* qbase = qkv + ((size_t)(b * Sn + q0)) * TDn + h * DHn;
    const float* kbase = qkv + ((size_t)(b * Sn)) * TDn + Dn + h * DHn;
    const float* vbase = kbase + Dn;

    for (int idx = tid; idx < 64 * 32; idx += 256) {
        int r = idx >> 5, c4 = (idx & 31) * 4;
        float4 v = *(const float4*)(qbase + (size_t)r * TDn + c4);
        float* dst = &Qs[r * QSTR + c4];
        dst[0] = v.x; dst[1] = v.y; dst[2] = v.z; dst[3] = v.w;
    }
    if (tid < 64) { row_m[tid] = -1e30f; row_l[tid] = 0.f; }

    float o[4][8];
#pragma unroll
    for (int i = 0; i < 4; i++)
#pragma unroll
        for (int c = 0; c < 8; c++) o[i][c] = 0.f;

    const float scale = 0.08838834764831845f;

    for (int kb = 0; kb <= qb; kb++) {
        __syncthreads();
        const int k0 = kb * 64;
        for (int idx = tid; idx < 64 * 32; idx += 256) {
            int r = idx >> 5, c4 = (idx & 31) * 4;
            const size_t goff = (size_t)(k0 + r) * TDn + c4;
            float4 kv = *(const float4*)(kbase + goff);
            float* kd = &Ks[r * QSTR + c4];
            kd[0] = kv.x; kd[1] = kv.y; kd[2] = kv.z; kd[3] = kv.w;
            float4 vv = *(const float4*)(vbase + goff);
            *(float4*)&Vs[r * VSTR + c4] = vv;
        }
        __syncthreads();

        float s[4][4];
#pragma unroll
        for (int i = 0; i < 4; i++)
#pragma unroll
            for (int j = 0; j < 4; j++) s[i][j] = 0.f;

        const float* q0p = &Qs[(ty * 4 + 0) * QSTR];
        const float* q1p = &Qs[(ty * 4 + 1) * QSTR];
        const float* q2p = &Qs[(ty * 4 + 2) * QSTR];
        const float* q3p = &Qs[(ty * 4 + 3) * QSTR];
        const float* k0p = &Ks[(tx * 4 + 0) * QSTR];
        const float* k1p = &Ks[(tx * 4 + 1) * QSTR];
        const float* k2p = &Ks[(tx * 4 + 2) * QSTR];
        const float* k3p = &Ks[(tx * 4 + 3) * QSTR];

#pragma unroll 4
        for (int d = 0; d < DHn; d++) {
            float qv[4], kv[4];
            qv[0] = q0p[d]; qv[1] = q1p[d]; qv[2] = q2p[d]; qv[3] = q3p[d];
            kv[0] = k0p[d]; kv[1] = k1p[d]; kv[2] = k2p[d]; kv[3] = k3p[d];
#pragma unroll
            for (int i = 0; i < 4; i++)
#pragma unroll
                for (int j = 0; j < 4; j++)
                    s[i][j] = fmaf(qv[i], kv[j], s[i][j]);
        }

        const bool diag = (kb == qb);
#pragma unroll
        for (int i = 0; i < 4; i++) {
#pragma unroll
            for (int j = 0; j < 4; j++) {
                float val = s[i][j] * scale;
                if (diag && (tx * 4 + j > ty * 4 + i)) val = -1e30f;
                Ps[(ty * 4 + i) * PSTR + tx * 4 + j] = val;
            }
        }
        __syncthreads();

        {
            const int r = tid >> 2, part = tid & 3;
            float* prow = &Ps[r * PSTR + part * 16];
            float mx = -1e30f;
#pragma unroll
            for (int j = 0; j < 16; j++) mx = fmaxf(mx, prow[j]);
            mx = fmaxf(mx, __shfl_xor_sync(0xffffffffu, mx, 1));
            mx = fmaxf(mx, __shfl_xor_sync(0xffffffffu, mx, 2));
            const float m_old = row_m[r];
            const float m_new = fmaxf(m_old, mx);
            float sum = 0.f;
#pragma unroll
            for (int j = 0; j < 16; j++) {
                float p = __expf(prow[j] - m_new);
                prow[j] = p;
                sum += p;
            }
            sum += __shfl_xor_sync(0xffffffffu, sum, 1);
            sum += __shfl_xor_sync(0xffffffffu, sum, 2);
            if (part == 0) {
                float alpha = __expf(m_old - m_new);
                row_l[r] = row_l[r] * alpha + sum;
                row_m[r] = m_new;
                row_a[r] = alpha;
            }
        }
        __syncthreads();

        float al[4];
#pragma unroll
        for (int i = 0; i < 4; i++) al[i] = row_a[ty * 4 + i];
#pragma unroll
        for (int i = 0; i < 4; i++)
#pragma unroll
            for (int c = 0; c < 8; c++) o[i][c] *= al[i];

#pragma unroll 2
        for (int j = 0; j < 64; j++) {
            float p[4];
#pragma unroll
            for (int i = 0; i < 4; i++) p[i] = Ps[(ty * 4 + i) * PSTR + j];
            float4 v0 = *(const float4*)&Vs[j * VSTR + tx * 8];
            float4 v1 = *(const float4*)&Vs[j * VSTR + tx * 8 + 4];
#pragma unroll
            for (int i = 0; i < 4; i++) {
                o[i][0] = fmaf(p[i], v0.x, o[i][0]);
                o[i][1] = fmaf(p[i], v0.y, o[i][1]);
                o[i][2] = fmaf(p[i], v0.z, o[i][2]);
                o[i][3] = fmaf(p[i], v0.w, o[i][3]);
                o[i][4] = fmaf(p[i], v1.x, o[i][4]);
                o[i][5] = fmaf(p[i], v1.y, o[i][5]);
                o[i][6] = fmaf(p[i], v1.z, o[i][6]);
                o[i][7] = fmaf(p[i], v1.w, o[i][7]);
            }
        }
    }

#pragma unroll
    for (int i = 0; i < 4; i++) {
        const int r = ty * 4 + i;
        const float inv = 1.0f / row_l[r];
        float* yp = Y + ((size_t)(b * Sn + q0 + r)) * Dn + h * DHn + tx * 8;
        float4 o0, o1;
        o0.x = o[i][0] * inv; o0.y = o[i][1] * inv;
        o0.z = o[i][2] * inv; o0.w = o[i][3] * inv;
        o1.x = o[i][4] * inv; o1.y = o[i][5] * inv;
        o1.z = o[i][6] * inv; o1.w = o[i][7] * inv;
        *(float4*)(yp) = o0;
        *(float4*)(yp + 4) = o1;
    }
}

// ---------------------------------------------------------------------------
extern "C" void kernel_launch(void* const* d_in, const int* in_sizes, int n_in,
                              void* d_out, int out_size)
{
    (void)in_sizes; (void)n_in; (void)out_size;
    const float* x      = (const float*)d_in[0];
    const float* qkv_w  = (const float*)d_in[1];
    const float* qkv_b  = (const float*)d_in[2];
    const float* out_w  = (const float*)d_in[3];
    const float* out_b  = (const float*)d_in[4];
    float* out = (float*)d_out;

    float *qkv, *y;
    cudaGetSymbolAddress((void**)&qkv, g_qkv);
    cudaGetSymbolAddress((void**)&y, g_y);

    cudaFuncSetAttribute(mma_gemm_bias,
                         cudaFuncAttributeMaxDynamicSharedMemorySize, GEMM_SMEM);

    // 1) QKV projection: [8192,2048] @ [6144,2048]^T (mma.sync tf32)
    {
        dim3 grid(TDn / 128, NROWS / 128);
        mma_gemm_bias<<<grid, 256, GEMM_SMEM>>>(x, qkv_w, qkv_b, qkv,
                                                NROWS, TDn, Dn);
    }

    // 2) RoPE on q,k
    {
        int total = Bn * Sn * Hn * (DHn / 2);
        rope_kernel<<<(total + 255) / 256, 256>>>(qkv);
    }

    // 3) Flash attention (fp32 SIMT)
    {
        const int smem_bytes = (64 * QSTR * 2 + 64 * VSTR + 64 * PSTR + 3 * 64) * sizeof(float);
        cudaFuncSetAttribute(flash_attn_kernel,
                             cudaFuncAttributeMaxDynamicSharedMemorySize, smem_bytes);
        dim3 grid(Sn / 64, Bn * Hn);
        flash_attn_kernel<<<grid, 256, smem_bytes>>>(qkv, y);
    }

    // 4) Output projection: [8192,2048] @ [2048,2048]^T (mma.sync tf32)
    {
        dim3 grid(Dn / 128, NROWS / 128);
        mma_gemm_bias<<<grid, 256, GEMM_SMEM>>>(y, out_w, out_b, out,
                                                NROWS, Dn, Dn);
    }
}

// round 4
// speedup vs baseline: 3.0363x; 1.7451x over previous
#include <cuda_runtime.h>
#include <cstdint>
#include <math.h>

// Problem constants
#define Bn 4
#define Sn 2048
#define Dn 2048
#define Hn 16
#define DHn 128
#define TDn 6144            // 3*D
#define NROWS (Bn*Sn)       // 8192

// Scratch (device globals; no cudaMalloc allowed)
__device__ float g_qkv[(size_t)NROWS * TDn];   // 201 MB
__device__ float g_y[(size_t)NROWS * Dn];      // 67 MB

__device__ __forceinline__ uint32_t f2tf32(float x) {
    uint32_t r;
    asm("cvt.rna.tf32.f32 %0, %1;" : "=r"(r) : "f"(x));
    return r;
}

__device__ __forceinline__ void mma_tf32(float* d,
                                         uint32_t a0, uint32_t a1,
                                         uint32_t a2, uint32_t a3,
                                         uint32_t b0, uint32_t b1) {
    asm volatile(
        "mma.sync.aligned.m16n8k8.row.col.f32.tf32.tf32.f32 "
        "{%0,%1,%2,%3}, {%4,%5,%6,%7}, {%8,%9}, {%0,%1,%2,%3};"
        : "+f"(d[0]), "+f"(d[1]), "+f"(d[2]), "+f"(d[3])
        : "r"(a0), "r"(a1), "r"(a2), "r"(a3), "r"(b0), "r"(b1));
}

// ---------------------------------------------------------------------------
// mma.sync tf32 GEMM: C[M,N] = A[M,K] @ W[N,K]^T + bias[N]   (unchanged R3)
// ---------------------------------------------------------------------------
#define KC 32
#define ASTR 36
#define TILE_F (128 * ASTR)
#define GEMM_SMEM (4 * TILE_F * 4)

__global__ __launch_bounds__(256) void mma_gemm_bias(
    const float* __restrict__ A, const float* __restrict__ W,
    const float* __restrict__ bias, float* __restrict__ C,
    int M, int N, int K)
{
    extern __shared__ float sm[];
    const int tid = threadIdx.x;
    const int wid = tid >> 5;
    const int lid = tid & 31;
    const int g   = lid >> 2;
    const int tg  = lid & 3;
    const int wm  = wid >> 2;
    const int wn  = wid & 3;
    const int m0 = blockIdx.y << 7;
    const int n0 = blockIdx.x << 7;

    float* Abuf[2] = { sm,              sm + TILE_F };
    float* Bbuf[2] = { sm + 2 * TILE_F, sm + 3 * TILE_F };

    const float* Abase = A + (size_t)m0 * K;
    const float* Wbase = W + (size_t)n0 * K;

    float acc[4][4][4];
#pragma unroll
    for (int mi = 0; mi < 4; mi++)
#pragma unroll
        for (int ni = 0; ni < 4; ni++)
#pragma unroll
            for (int r = 0; r < 4; r++) acc[mi][ni][r] = 0.f;

    const int nc = K / KC;
    float4 ra[4], rb[4];

    auto load_regs = [&](int c) {
        const int k0 = c * KC;
#pragma unroll
        for (int i = 0; i < 4; i++) {
            int idx = i * 256 + tid;
            int r  = idx >> 3;
            int c4 = (idx & 7) << 2;
            ra[i] = *(const float4*)(Abase + (size_t)r * K + k0 + c4);
            rb[i] = *(const float4*)(Wbase + (size_t)r * K + k0 + c4);
        }
    };

    auto sts_regs = [&](int buf) {
#pragma unroll
        for (int i = 0; i < 4; i++) {
            int idx = i * 256 + tid;
            int r  = idx >> 3;
            int c4 = (idx & 7) << 2;
            uint4 av = make_uint4(f2tf32(ra[i].x), f2tf32(ra[i].y),
                                  f2tf32(ra[i].z), f2tf32(ra[i].w));
            uint4 bv = make_uint4(f2tf32(rb[i].x), f2tf32(rb[i].y),
                                  f2tf32(rb[i].z), f2tf32(rb[i].w));
            *(uint4*)&Abuf[buf][r * ASTR + c4] = av;
            *(uint4*)&Bbuf[buf][r * ASTR + c4] = bv;
        }
    };

    auto mma_chunk = [&](int buf) {
        const float* As = Abuf[buf];
        const float* Bs = Bbuf[buf];
#pragma unroll
        for (int ks = 0; ks < 4; ks++) {
            const int kc = ks * 8;
            uint32_t af[4][4], bf[4][2];
#pragma unroll
            for (int mi = 0; mi < 4; mi++) {
                const float* ap = &As[(wm * 64 + mi * 16 + g) * ASTR + kc + tg];
                af[mi][0] = __float_as_uint(ap[0]);
                af[mi][1] = __float_as_uint(ap[8 * ASTR]);
                af[mi][2] = __float_as_uint(ap[4]);
                af[mi][3] = __float_as_uint(ap[8 * ASTR + 4]);
            }
#pragma unroll
            for (int ni = 0; ni < 4; ni++) {
                const float* bp = &Bs[(wn * 32 + ni * 8 + g) * ASTR + kc + tg];
                bf[ni][0] = __float_as_uint(bp[0]);
                bf[ni][1] = __float_as_uint(bp[4]);
            }
#pragma unroll
            for (int mi = 0; mi < 4; mi++)
#pragma unroll
                for (int ni = 0; ni < 4; ni++)
                    mma_tf32(acc[mi][ni],
                             af[mi][0], af[mi][1], af[mi][2], af[mi][3],
                             bf[ni][0], bf[ni][1]);
        }
    };

    load_regs(0);
    sts_regs(0);
    __syncthreads();

    for (int c = 0; c < nc; c++) {
        if (c + 1 < nc) load_regs(c + 1);
        mma_chunk(c & 1);
        __syncthreads();
        if (c + 1 < nc) {
            sts_regs((c + 1) & 1);
            __syncthreads();
        }
    }

#pragma unroll
    for (int ni = 0; ni < 4; ni++) {
        const int col = n0 + wn * 32 + ni * 8 + 2 * tg;
        const float2 bj = *(const float2*)&bias[col];
#pragma unroll
        for (int mi = 0; mi < 4; mi++) {
            const int row = m0 + wm * 64 + mi * 16 + g;
            float2 o0, o1;
            o0.x = acc[mi][ni][0] + bj.x;
            o0.y = acc[mi][ni][1] + bj.y;
            o1.x = acc[mi][ni][2] + bj.x;
            o1.y = acc[mi][ni][3] + bj.y;
            *(float2*)&C[(size_t)row * N + col] = o0;
            *(float2*)&C[(size_t)(row + 8) * N + col] = o1;
        }
    }
}

// ---------------------------------------------------------------------------
// RoPE applied in-place to q and k halves of g_qkv (unchanged)
// ---------------------------------------------------------------------------
__global__ __launch_bounds__(256) void rope_kernel(float* __restrict__ qkv)
{
    int idx = blockIdx.x * blockDim.x + threadIdx.x;
    const int total = Bn * Sn * Hn * (DHn / 2);
    if (idx >= total) return;

    int d2 = idx & 63;
    int h  = (idx >> 6) & 15;
    int bs = idx >> 10;
    int s  = bs & (Sn - 1);

    float freq  = powf(10000.0f, -(float)d2 / 64.0f);
    float angle = (float)s * freq;
    float sn, cs;
    sincosf(angle, &sn, &cs);

    size_t base = (size_t)bs * TDn + h * DHn + 2 * d2;

    float x1 = qkv[base], x2 = qkv[base + 1];
    qkv[base]     = x1 * cs - x2 * sn;
    qkv[base + 1] = x1 * sn + x2 * cs;
    float y1 = qkv[base + Dn], y2 = qkv[base + Dn + 1];
    qkv[base + Dn]     = y1 * cs - y2 * sn;
    qkv[base + Dn + 1] = y1 * sn + y2 * cs;
}

// ---------------------------------------------------------------------------
// Tensor-core flash attention (causal), tf32 mma.
// CTA: 128 q-rows, 256 threads = 8 warps; each warp owns 16 q-rows.
// K-tile: 64 keys. Q frags + O accum in registers; K/V/P in smem.
// ---------------------------------------------------------------------------
#define KSTR 132   // K smem stride (floats): B-frag bank = 4g+tg (bijective)
#define VSTR 136   // V smem stride: B-frag bank = 8tg+g (bijective)
#define PSTRW 132  // P smem stride
#define FA_SMEM ((64 * KSTR + 64 * VSTR + 128 * PSTRW) * 4)

__global__ __launch_bounds__(256) void flash_attn_tc(
    const float* __restrict__ qkv, float* __restrict__ Y)
{
    extern __shared__ float sm[];
    float* Ks = sm;                     // [64][KSTR]
    float* Vs = Ks + 64 * KSTR;         // [64][VSTR]
    float* Pw = Vs + 64 * VSTR;         // [128][PSTRW]

    const int tid = threadIdx.x;
    const int wid = tid >> 5;
    const int lid = tid & 31;
    const int g   = lid >> 2;
    const int tg  = lid & 3;
    const int qb  = blockIdx.x;
    const int q0  = qb * 128;
    const int bh  = blockIdx.y;
    const int b   = bh >> 4;
    const int h   = bh & 15;

    const int row0 = q0 + wid * 16 + g;          // abs q row for c0/c1
    const float scale = 0.08838834764831845f;    // 1/sqrt(128)

    // Q fragments (scaled, tf32) live in registers for the whole kernel
    const float* qptr = qkv + ((size_t)(b * Sn + row0)) * TDn + h * DHn;
    uint32_t qf[16][4];
#pragma unroll
    for (int kt = 0; kt < 16; kt++) {
        qf[kt][0] = f2tf32(qptr[kt * 8 + tg] * scale);
        qf[kt][1] = f2tf32(qptr[(size_t)8 * TDn + kt * 8 + tg] * scale);
        qf[kt][2] = f2tf32(qptr[kt * 8 + tg + 4] * scale);
        qf[kt][3] = f2tf32(qptr[(size_t)8 * TDn + kt * 8 + tg + 4] * scale);
    }

    float ofr[16][4];
#pragma unroll
    for (int nt = 0; nt < 16; nt++)
#pragma unroll
        for (int r = 0; r < 4; r++) ofr[nt][r] = 0.f;

    float m0 = -1e30f, m1 = -1e30f, l0 = 0.f, l1 = 0.f;

    const float* kbase = qkv + ((size_t)(b * Sn)) * TDn + Dn + h * DHn;
    const float* vbase = kbase + Dn;
    float* prow = Pw + (wid * 16) * PSTRW;

    const int nkb = 2 * qb + 2;
    for (int kb = 0; kb < nkb; kb++) {
        __syncthreads();
        const int k0 = kb * 64;

        // Load K,V tiles (tf32-converted). One row per warp-iter, coalesced.
#pragma unroll
        for (int i = 0; i < 8; i++) {
            int idx = tid + i * 256;
            int r  = idx >> 5;
            int c4 = (idx & 31) << 2;
            const size_t go = (size_t)(k0 + r) * TDn + c4;
            float4 kv = *(const float4*)(kbase + go);
            uint4 ku = make_uint4(f2tf32(kv.x), f2tf32(kv.y),
                                  f2tf32(kv.z), f2tf32(kv.w));
            *(uint4*)&Ks[r * KSTR + c4] = ku;
            float4 vv = *(const float4*)(vbase + go);
            uint4 vu = make_uint4(f2tf32(vv.x), f2tf32(vv.y),
                                  f2tf32(vv.z), f2tf32(vv.w));
            *(uint4*)&Vs[r * VSTR + c4] = vu;
        }
        __syncthreads();

        // S = (Q*scale) K^T : warp computes 16x64
        float sc[8][4];
#pragma unroll
        for (int nt = 0; nt < 8; nt++)
#pragma unroll
            for (int r = 0; r < 4; r++) sc[nt][r] = 0.f;

#pragma unroll
        for (int kt = 0; kt < 16; kt++) {
#pragma unroll
            for (int nt = 0; nt < 8; nt++) {
                const float* bp = &Ks[(nt * 8 + g) * KSTR + kt * 8 + tg];
                uint32_t b0 = __float_as_uint(bp[0]);
                uint32_t b1 = __float_as_uint(bp[4]);
                mma_tf32(sc[nt], qf[kt][0], qf[kt][1], qf[kt][2], qf[kt][3],
                         b0, b1);
            }
        }

        // Causal mask (only the last two k-tiles can violate)
        if (kb >= 2 * qb) {
#pragma unroll
            for (int nt = 0; nt < 8; nt++) {
                int col = k0 + nt * 8 + 2 * tg;
                if (col > row0)     sc[nt][0] = -1e30f;
                if (col + 1 > row0) sc[nt][1] = -1e30f;
                if (col > row0 + 8)     sc[nt][2] = -1e30f;
                if (col + 1 > row0 + 8) sc[nt][3] = -1e30f;
            }
        }

        // Online softmax (rows row0 and row0+8)
        float mx0 = -1e30f, mx1 = -1e30f;
#pragma unroll
        for (int nt = 0; nt < 8; nt++) {
            mx0 = fmaxf(mx0, fmaxf(sc[nt][0], sc[nt][1]));
            mx1 = fmaxf(mx1, fmaxf(sc[nt][2], sc[nt][3]));
        }
        mx0 = fmaxf(mx0, __shfl_xor_sync(0xffffffffu, mx0, 1));
        mx0 = fmaxf(mx0, __shfl_xor_sync(0xffffffffu, mx0, 2));
        mx1 = fmaxf(mx1, __shfl_xor_sync(0xffffffffu, mx1, 1));
        mx1 = fmaxf(mx1, __shfl_xor_sync(0xffffffffu, mx1, 2));

        const float mn0 = fmaxf(m0, mx0);
        const float mn1 = fmaxf(m1, mx1);
        const float a0 = __expf(m0 - mn0);
        const float a1 = __expf(m1 - mn1);
        m0 = mn0; m1 = mn1;

        float s0 = 0.f, s1 = 0.f;
#pragma unroll
        for (int nt = 0; nt < 8; nt++) {
            sc[nt][0] = __expf(sc[nt][0] - mn0);
            sc[nt][1] = __expf(sc[nt][1] - mn0);
            sc[nt][2] = __expf(sc[nt][2] - mn1);
            sc[nt][3] = __expf(sc[nt][3] - mn1);
            s0 += sc[nt][0] + sc[nt][1];
            s1 += sc[nt][2] + sc[nt][3];
        }
        s0 += __shfl_xor_sync(0xffffffffu, s0, 1);
        s0 += __shfl_xor_sync(0xffffffffu, s0, 2);
        s1 += __shfl_xor_sync(0xffffffffu, s1, 1);
        s1 += __shfl_xor_sync(0xffffffffu, s1, 2);
        l0 = l0 * a0 + s0;
        l1 = l1 * a1 + s1;

#pragma unroll
        for (int nt = 0; nt < 16; nt++) {
            ofr[nt][0] *= a0; ofr[nt][1] *= a0;
            ofr[nt][2] *= a1; ofr[nt][3] *= a1;
        }

        // Write P (tf32) to warp-private smem
        __syncwarp();
#pragma unroll
        for (int nt = 0; nt < 8; nt++) {
            const int col = nt * 8 + 2 * tg;
            prow[g * PSTRW + col]           = __uint_as_float(f2tf32(sc[nt][0]));
            prow[g * PSTRW + col + 1]       = __uint_as_float(f2tf32(sc[nt][1]));
            prow[(g + 8) * PSTRW + col]     = __uint_as_float(f2tf32(sc[nt][2]));
            prow[(g + 8) * PSTRW + col + 1] = __uint_as_float(f2tf32(sc[nt][3]));
        }
        __syncwarp();

        // O += P @ V : A-frags from Pw, B-frags straight from row-major Vs
#pragma unroll
        for (int kt = 0; kt < 8; kt++) {
            uint32_t pa0 = __float_as_uint(prow[g * PSTRW + kt * 8 + tg]);
            uint32_t pa1 = __float_as_uint(prow[(g + 8) * PSTRW + kt * 8 + tg]);
            uint32_t pa2 = __float_as_uint(prow[g * PSTRW + kt * 8 + tg + 4]);
            uint32_t pa3 = __float_as_uint(prow[(g + 8) * PSTRW + kt * 8 + tg + 4]);
#pragma unroll
            for (int nt = 0; nt < 16; nt++) {
                uint32_t b0 = __float_as_uint(Vs[(kt * 8 + tg) * VSTR + nt * 8 + g]);
                uint32_t b1 = __float_as_uint(Vs[(kt * 8 + tg + 4) * VSTR + nt * 8 + g]);
                mma_tf32(ofr[nt], pa0, pa1, pa2, pa3, b0, b1);
            }
        }
    }

    // Epilogue: normalize and store
    const float inv0 = 1.0f / l0;
    const float inv1 = 1.0f / l1;
    float* yrow = Y + ((size_t)(b * Sn + row0)) * Dn + h * DHn;
#pragma unroll
    for (int nt = 0; nt < 16; nt++) {
        const int col = nt * 8 + 2 * tg;
        float2 o0, o1;
        o0.x = ofr[nt][0] * inv0; o0.y = ofr[nt][1] * inv0;
        o1.x = ofr[nt][2] * inv1; o1.y = ofr[nt][3] * inv1;
        *(float2*)&yrow[col] = o0;
        *(float2*)&yrow[(size_t)8 * Dn + col] = o1;
    }
}

// ---------------------------------------------------------------------------
extern "C" void kernel_launch(void* const* d_in, const int* in_sizes, int n_in,
                              void* d_out, int out_size)
{
    (void)in_sizes; (void)n_in; (void)out_size;
    const float* x      = (const float*)d_in[0];
    const float* qkv_w  = (const float*)d_in[1];
    const float* qkv_b  = (const float*)d_in[2];
    const float* out_w  = (const float*)d_in[3];
    const float* out_b  = (const float*)d_in[4];
    float* out = (float*)d_out;

    float *qkv, *y;
    cudaGetSymbolAddress((void**)&qkv, g_qkv);
    cudaGetSymbolAddress((void**)&y, g_y);

    cudaFuncSetAttribute(mma_gemm_bias,
                         cudaFuncAttributeMaxDynamicSharedMemorySize, GEMM_SMEM);
    cudaFuncSetAttribute(flash_attn_tc,
                         cudaFuncAttributeMaxDynamicSharedMemorySize, FA_SMEM);

    // 1) QKV projection (mma.sync tf32)
    {
        dim3 grid(TDn / 128, NROWS / 128);
        mma_gemm_bias<<<grid, 256, GEMM_SMEM>>>(x, qkv_w, qkv_b, qkv,
                                                NROWS, TDn, Dn);
    }

    // 2) RoPE on q,k
    {
        int total = Bn * Sn * Hn * (DHn / 2);
        rope_kernel<<<(total + 255) / 256, 256>>>(qkv);
    }

    // 3) Flash attention (tensor-core tf32)
    {
        dim3 grid(Sn / 128, Bn * Hn);
        flash_attn_tc<<<grid, 256, FA_SMEM>>>(qkv, y);
    }

    // 4) Output projection (mma.sync tf32)
    {
        dim3 grid(Dn / 128, NROWS / 128);
        mma_gemm_bias<<<grid, 256, GEMM_SMEM>>>(y, out_w, out_b, out,
                                                NROWS, Dn, Dn);
    }
}

// round 5
// speedup vs baseline: 3.7980x; 1.2509x over previous
#include <cuda_runtime.h>
#include <cstdint>
#include <math.h>

// Problem constants
#define Bn 4
#define Sn 2048
#define Dn 2048
#define Hn 16
#define DHn 128
#define TDn 6144            // 3*D
#define NROWS (Bn*Sn)       // 8192

// Scratch (device globals; no cudaMalloc allowed)
__device__ float g_qkv[(size_t)NROWS * TDn];   // 201 MB
__device__ float g_y[(size_t)NROWS * Dn];      // 67 MB  (tf32-formatted)
__device__ float g_xt[(size_t)NROWS * Dn];     // 67 MB  x  pre-converted
__device__ float g_wq[(size_t)TDn * Dn];       // 50 MB  qkv_w pre-converted
__device__ float g_wo[(size_t)Dn * Dn];        // 17 MB  out_w pre-converted

__device__ __forceinline__ uint32_t f2tf32(float x) {
    uint32_t r;
    asm("cvt.rna.tf32.f32 %0, %1;" : "=r"(r) : "f"(x));
    return r;
}

__device__ __forceinline__ void mma_tf32(float* d,
                                         uint32_t a0, uint32_t a1,
                                         uint32_t a2, uint32_t a3,
                                         uint32_t b0, uint32_t b1) {
    asm volatile(
        "mma.sync.aligned.m16n8k8.row.col.f32.tf32.tf32.f32 "
        "{%0,%1,%2,%3}, {%4,%5,%6,%7}, {%8,%9}, {%0,%1,%2,%3};"
        : "+f"(d[0]), "+f"(d[1]), "+f"(d[2]), "+f"(d[3])
        : "r"(a0), "r"(a1), "r"(a2), "r"(a3), "r"(b0), "r"(b1));
}

__device__ __forceinline__ void cp16(void* smem_ptr, const void* gptr) {
    uint32_t sa = (uint32_t)__cvta_generic_to_shared(smem_ptr);
    asm volatile("cp.async.cg.shared.global [%0], [%1], 16;"
                 :: "r"(sa), "l"(gptr));
}
#define CP_COMMIT() asm volatile("cp.async.commit_group;" ::: "memory")
#define CP_WAIT(n)  asm volatile("cp.async.wait_group %0;" :: "n"(n) : "memory")

// ---------------------------------------------------------------------------
// Pre-convert fp32 -> tf32-formatted fp32 (vectorized)
// ---------------------------------------------------------------------------
__global__ __launch_bounds__(256) void conv_tf32_kernel(
    const float* __restrict__ in, float* __restrict__ out, int n4)
{
    int i = blockIdx.x * blockDim.x + threadIdx.x;
    if (i >= n4) return;
    float4 v = ((const float4*)in)[i];
    uint4 u = make_uint4(f2tf32(v.x), f2tf32(v.y), f2tf32(v.z), f2tf32(v.w));
    ((uint4*)out)[i] = u;
}

// ---------------------------------------------------------------------------
// cp.async tf32 GEMM: C[M,N] = A[M,K] @ W[N,K]^T + bias[N]
// A, W must already be tf32-formatted fp32.
// CTA 128x128, 8 warps (2m x 4n), warp tile 64x32. KC=16, 4 stages.
// smem stride 20 floats (conflict-free fragment LDS). 2 CTAs/SM.
// ---------------------------------------------------------------------------
#define KC2 16
#define STG 4
#define STR2 20
#define TILE2 (128 * STR2)                    // 2560 floats per tile
#define GEMM2_SMEM (STG * 2 * TILE2 * 4)      // 81920 bytes

__global__ void __launch_bounds__(256, 2) mma_gemm_ca(
    const float* __restrict__ A, const float* __restrict__ W,
    const float* __restrict__ bias, float* __restrict__ C,
    int M, int N, int K)
{
    extern __shared__ float sm[];
    const int tid = threadIdx.x;
    const int wid = tid >> 5;
    const int lid = tid & 31;
    const int g   = lid >> 2;
    const int tg  = lid & 3;
    const int wm  = wid >> 2;       // 0..1
    const int wn  = wid & 3;        // 0..3
    const int m0 = blockIdx.y << 7;
    const int n0 = blockIdx.x << 7;

    const float* Abase = A + (size_t)m0 * K;
    const float* Wbase = W + (size_t)n0 * K;

    // per-thread load mapping: 2 float4 for A + 2 for B per chunk
    const int lrow = tid >> 2;            // 0..63
    const int lc4  = (tid & 3) << 2;      // 0,4,8,12

    float acc[4][4][4];
#pragma unroll
    for (int mi = 0; mi < 4; mi++)
#pragma unroll
        for (int ni = 0; ni < 4; ni++)
#pragma unroll
            for (int r = 0; r < 4; r++) acc[mi][ni][r] = 0.f;

    const int nc = K / KC2;

    auto issue_load = [&](int stage, int chunk) {
        const int k0 = chunk * KC2;
        float* As = sm + stage * 2 * TILE2;
        float* Bs = As + TILE2;
#pragma unroll
        for (int i = 0; i < 2; i++) {
            const int row = lrow + i * 64;
            cp16(&As[row * STR2 + lc4], Abase + (size_t)row * K + k0 + lc4);
            cp16(&Bs[row * STR2 + lc4], Wbase + (size_t)row * K + k0 + lc4);
        }
    };

    auto compute = [&](int stage) {
        const float* As = sm + stage * 2 * TILE2;
        const float* Bs = As + TILE2;
#pragma unroll
        for (int ks = 0; ks < 2; ks++) {
            const int kc = ks * 8;
            uint32_t af[4][4], bf[4][2];
#pragma unroll
            for (int mi = 0; mi < 4; mi++) {
                const float* ap = &As[(wm * 64 + mi * 16 + g) * STR2 + kc + tg];
                af[mi][0] = __float_as_uint(ap[0]);
                af[mi][1] = __float_as_uint(ap[8 * STR2]);
                af[mi][2] = __float_as_uint(ap[4]);
                af[mi][3] = __float_as_uint(ap[8 * STR2 + 4]);
            }
#pragma unroll
            for (int ni = 0; ni < 4; ni++) {
                const float* bp = &Bs[(wn * 32 + ni * 8 + g) * STR2 + kc + tg];
                bf[ni][0] = __float_as_uint(bp[0]);
                bf[ni][1] = __float_as_uint(bp[4]);
            }
#pragma unroll
            for (int mi = 0; mi < 4; mi++)
#pragma unroll
                for (int ni = 0; ni < 4; ni++)
                    mma_tf32(acc[mi][ni],
                             af[mi][0], af[mi][1], af[mi][2], af[mi][3],
                             bf[ni][0], bf[ni][1]);
        }
    };

    // prologue: fill STG-1 stages
#pragma unroll
    for (int s = 0; s < STG - 1; s++) {
        issue_load(s, s);
        CP_COMMIT();
    }

    for (int c = 0; c < nc; c++) {
        CP_WAIT(STG - 2);
        __syncthreads();
        const int nxt = c + STG - 1;
        if (nxt < nc) issue_load(nxt & (STG - 1), nxt);
        CP_COMMIT();
        compute(c & (STG - 1));
    }

    // epilogue: write C + bias
#pragma unroll
    for (int ni = 0; ni < 4; ni++) {
        const int col = n0 + wn * 32 + ni * 8 + 2 * tg;
        const float2 bj = *(const float2*)&bias[col];
#pragma unroll
        for (int mi = 0; mi < 4; mi++) {
            const int row = m0 + wm * 64 + mi * 16 + g;
            float2 o0, o1;
            o0.x = acc[mi][ni][0] + bj.x;
            o0.y = acc[mi][ni][1] + bj.y;
            o1.x = acc[mi][ni][2] + bj.x;
            o1.y = acc[mi][ni][3] + bj.y;
            *(float2*)&C[(size_t)row * N + col] = o0;
            *(float2*)&C[(size_t)(row + 8) * N + col] = o1;
        }
    }
}

// ---------------------------------------------------------------------------
// RoPE applied in-place to q and k halves of g_qkv (unchanged)
// ---------------------------------------------------------------------------
__global__ __launch_bounds__(256) void rope_kernel(float* __restrict__ qkv)
{
    int idx = blockIdx.x * blockDim.x + threadIdx.x;
    const int total = Bn * Sn * Hn * (DHn / 2);
    if (idx >= total) return;

    int d2 = idx & 63;
    int h  = (idx >> 6) & 15;
    int bs = idx >> 10;
    int s  = bs & (Sn - 1);

    float freq  = powf(10000.0f, -(float)d2 / 64.0f);
    float angle = (float)s * freq;
    float sn, cs;
    sincosf(angle, &sn, &cs);

    size_t base = (size_t)bs * TDn + h * DHn + 2 * d2;

    float x1 = qkv[base], x2 = qkv[base + 1];
    qkv[base]     = x1 * cs - x2 * sn;
    qkv[base + 1] = x1 * sn + x2 * cs;
    float y1 = qkv[base + Dn], y2 = qkv[base + Dn + 1];
    qkv[base + Dn]     = y1 * cs - y2 * sn;
    qkv[base + Dn + 1] = y1 * sn + y2 * cs;
}

// ---------------------------------------------------------------------------
// Tensor-core flash attention (causal), tf32 mma. (R4, epilogue emits tf32)
// ---------------------------------------------------------------------------
#define KSTR 132
#define VSTR 136
#define PSTRW 132
#define FA_SMEM ((64 * KSTR + 64 * VSTR + 128 * PSTRW) * 4)

__global__ __launch_bounds__(256) void flash_attn_tc(
    const float* __restrict__ qkv, float* __restrict__ Y)
{
    extern __shared__ float sm[];
    float* Ks = sm;
    float* Vs = Ks + 64 * KSTR;
    float* Pw = Vs + 64 * VSTR;

    const int tid = threadIdx.x;
    const int wid = tid >> 5;
    const int lid = tid & 31;
    const int g   = lid >> 2;
    const int tg  = lid & 3;
    const int qb  = blockIdx.x;
    const int q0  = qb * 128;
    const int bh  = blockIdx.y;
    const int b   = bh >> 4;
    const int h   = bh & 15;

    const int row0 = q0 + wid * 16 + g;
    const float scale = 0.08838834764831845f;

    const float* qptr = qkv + ((size_t)(b * Sn + row0)) * TDn + h * DHn;
    uint32_t qf[16][4];
#pragma unroll
    for (int kt = 0; kt < 16; kt++) {
        qf[kt][0] = f2tf32(qptr[kt * 8 + tg] * scale);
        qf[kt][1] = f2tf32(qptr[(size_t)8 * TDn + kt * 8 + tg] * scale);
        qf[kt][2] = f2tf32(qptr[kt * 8 + tg + 4] * scale);
        qf[kt][3] = f2tf32(qptr[(size_t)8 * TDn + kt * 8 + tg + 4] * scale);
    }

    float ofr[16][4];
#pragma unroll
    for (int nt = 0; nt < 16; nt++)
#pragma unroll
        for (int r = 0; r < 4; r++) ofr[nt][r] = 0.f;

    float m0 = -1e30f, m1 = -1e30f, l0 = 0.f, l1 = 0.f;

    const float* kbase = qkv + ((size_t)(b * Sn)) * TDn + Dn + h * DHn;
    const float* vbase = kbase + Dn;
    float* prow = Pw + (wid * 16) * PSTRW;

    const int nkb = 2 * qb + 2;
    for (int kb = 0; kb < nkb; kb++) {
        __syncthreads();
        const int k0 = kb * 64;

#pragma unroll
        for (int i = 0; i < 8; i++) {
            int idx = tid + i * 256;
            int r  = idx >> 5;
            int c4 = (idx & 31) << 2;
            const size_t go = (size_t)(k0 + r) * TDn + c4;
            float4 kv = *(const float4*)(kbase + go);
            uint4 ku = make_uint4(f2tf32(kv.x), f2tf32(kv.y),
                                  f2tf32(kv.z), f2tf32(kv.w));
            *(uint4*)&Ks[r * KSTR + c4] = ku;
            float4 vv = *(const float4*)(vbase + go);
            uint4 vu = make_uint4(f2tf32(vv.x), f2tf32(vv.y),
                                  f2tf32(vv.z), f2tf32(vv.w));
            *(uint4*)&Vs[r * VSTR + c4] = vu;
        }
        __syncthreads();

        float sc[8][4];
#pragma unroll
        for (int nt = 0; nt < 8; nt++)
#pragma unroll
            for (int r = 0; r < 4; r++) sc[nt][r] = 0.f;

#pragma unroll
        for (int kt = 0; kt < 16; kt++) {
#pragma unroll
            for (int nt = 0; nt < 8; nt++) {
                const float* bp = &Ks[(nt * 8 + g) * KSTR + kt * 8 + tg];
                uint32_t b0 = __float_as_uint(bp[0]);
                uint32_t b1 = __float_as_uint(bp[4]);
                mma_tf32(sc[nt], qf[kt][0], qf[kt][1], qf[kt][2], qf[kt][3],
                         b0, b1);
            }
        }

        if (kb >= 2 * qb) {
#pragma unroll
            for (int nt = 0; nt < 8; nt++) {
                int col = k0 + nt * 8 + 2 * tg;
                if (col > row0)     sc[nt][0] = -1e30f;
                if (col + 1 > row0) sc[nt][1] = -1e30f;
                if (col > row0 + 8)     sc[nt][2] = -1e30f;
                if (col + 1 > row0 + 8) sc[nt][3] = -1e30f;
            }
        }

        float mx0 = -1e30f, mx1 = -1e30f;
#pragma unroll
        for (int nt = 0; nt < 8; nt++) {
            mx0 = fmaxf(mx0, fmaxf(sc[nt][0], sc[nt][1]));
            mx1 = fmaxf(mx1, fmaxf(sc[nt][2], sc[nt][3]));
        }
        mx0 = fmaxf(mx0, __shfl_xor_sync(0xffffffffu, mx0, 1));
        mx0 = fmaxf(mx0, __shfl_xor_sync(0xffffffffu, mx0, 2));
        mx1 = fmaxf(mx1, __shfl_xor_sync(0xffffffffu, mx1, 1));
        mx1 = fmaxf(mx1, __shfl_xor_sync(0xffffffffu, mx1, 2));

        const float mn0 = fmaxf(m0, mx0);
        const float mn1 = fmaxf(m1, mx1);
        const float a0 = __expf(m0 - mn0);
        const float a1 = __expf(m1 - mn1);
        m0 = mn0; m1 = mn1;

        float s0 = 0.f, s1 = 0.f;
#pragma unroll
        for (int nt = 0; nt < 8; nt++) {
            sc[nt][0] = __expf(sc[nt][0] - mn0);
            sc[nt][1] = __expf(sc[nt][1] - mn0);
            sc[nt][2] = __expf(sc[nt][2] - mn1);
            sc[nt][3] = __expf(sc[nt][3] - mn1);
            s0 += sc[nt][0] + sc[nt][1];
            s1 += sc[nt][2] + sc[nt][3];
        }
        s0 += __shfl_xor_sync(0xffffffffu, s0, 1);
        s0 += __shfl_xor_sync(0xffffffffu, s0, 2);
        s1 += __shfl_xor_sync(0xffffffffu, s1, 1);
        s1 += __shfl_xor_sync(0xffffffffu, s1, 2);
        l0 = l0 * a0 + s0;
        l1 = l1 * a1 + s1;

#pragma unroll
        for (int nt = 0; nt < 16; nt++) {
            ofr[nt][0] *= a0; ofr[nt][1] *= a0;
            ofr[nt][2] *= a1; ofr[nt][3] *= a1;
        }

        __syncwarp();
#pragma unroll
        for (int nt = 0; nt < 8; nt++) {
            const int col = nt * 8 + 2 * tg;
            prow[g * PSTRW + col]           = __uint_as_float(f2tf32(sc[nt][0]));
            prow[g * PSTRW + col + 1]       = __uint_as_float(f2tf32(sc[nt][1]));
            prow[(g + 8) * PSTRW + col]     = __uint_as_float(f2tf32(sc[nt][2]));
            prow[(g + 8) * PSTRW + col + 1] = __uint_as_float(f2tf32(sc[nt][3]));
        }
        __syncwarp();

#pragma unroll
        for (int kt = 0; kt < 8; kt++) {
            uint32_t pa0 = __float_as_uint(prow[g * PSTRW + kt * 8 + tg]);
            uint32_t pa1 = __float_as_uint(prow[(g + 8) * PSTRW + kt * 8 + tg]);
            uint32_t pa2 = __float_as_uint(prow[g * PSTRW + kt * 8 + tg + 4]);
            uint32_t pa3 = __float_as_uint(prow[(g + 8) * PSTRW + kt * 8 + tg + 4]);
#pragma unroll
            for (int nt = 0; nt < 16; nt++) {
                uint32_t b0 = __float_as_uint(Vs[(kt * 8 + tg) * VSTR + nt * 8 + g]);
                uint32_t b1 = __float_as_uint(Vs[(kt * 8 + tg + 4) * VSTR + nt * 8 + g]);
                mma_tf32(ofr[nt], pa0, pa1, pa2, pa3, b0, b1);
            }
        }
    }

    // Epilogue: normalize, tf32-round (feeds tf32 GEMM directly), store
    const float inv0 = 1.0f / l0;
    const float inv1 = 1.0f / l1;
    float* yrow = Y + ((size_t)(b * Sn + row0)) * Dn + h * DHn;
#pragma unroll
    for (int nt = 0; nt < 16; nt++) {
        const int col = nt * 8 + 2 * tg;
        float2 o0, o1;
        o0.x = __uint_as_float(f2tf32(ofr[nt][0] * inv0));
        o0.y = __uint_as_float(f2tf32(ofr[nt][1] * inv0));
        o1.x = __uint_as_float(f2tf32(ofr[nt][2] * inv1));
        o1.y = __uint_as_float(f2tf32(ofr[nt][3] * inv1));
        *(float2*)&yrow[col] = o0;
        *(float2*)&yrow[(size_t)8 * Dn + col] = o1;
    }
}

// ---------------------------------------------------------------------------
extern "C" void kernel_launch(void* const* d_in, const int* in_sizes, int n_in,
                              void* d_out, int out_size)
{
    (void)in_sizes; (void)n_in; (void)out_size;
    const float* x      = (const float*)d_in[0];
    const float* qkv_w  = (const float*)d_in[1];
    const float* qkv_b  = (const float*)d_in[2];
    const float* out_w  = (const float*)d_in[3];
    const float* out_b  = (const float*)d_in[4];
    float* out = (float*)d_out;

    float *qkv, *y, *xt, *wq, *wo;
    cudaGetSymbolAddress((void**)&qkv, g_qkv);
    cudaGetSymbolAddress((void**)&y, g_y);
    cudaGetSymbolAddress((void**)&xt, g_xt);
    cudaGetSymbolAddress((void**)&wq, g_wq);
    cudaGetSymbolAddress((void**)&wo, g_wo);

    cudaFuncSetAttribute(mma_gemm_ca,
                         cudaFuncAttributeMaxDynamicSharedMemorySize, GEMM2_SMEM);
    cudaFuncSetAttribute(flash_attn_tc,
                         cudaFuncAttributeMaxDynamicSharedMemorySize, FA_SMEM);

    // 0) Pre-convert inputs to tf32 format
    {
        int n4x = (NROWS * Dn) / 4;
        conv_tf32_kernel<<<(n4x + 255) / 256, 256>>>(x, xt, n4x);
        int n4q = (TDn * Dn) / 4;
        conv_tf32_kernel<<<(n4q + 255) / 256, 256>>>(qkv_w, wq, n4q);
        int n4o = (Dn * Dn) / 4;
        conv_tf32_kernel<<<(n4o + 255) / 256, 256>>>(out_w, wo, n4o);
    }

    // 1) QKV projection (cp.async tf32 mma)
    {
        dim3 grid(TDn / 128, NROWS / 128);
        mma_gemm_ca<<<grid, 256, GEMM2_SMEM>>>(xt, wq, qkv_b, qkv,
                                               NROWS, TDn, Dn);
    }

    // 2) RoPE on q,k
    {
        int total = Bn * Sn * Hn * (DHn / 2);
        rope_kernel<<<(total + 255) / 256, 256>>>(qkv);
    }

    // 3) Flash attention (tensor-core tf32), emits tf32-formatted y
    {
        dim3 grid(Sn / 128, Bn * Hn);
        flash_attn_tc<<<grid, 256, FA_SMEM>>>(qkv, y);
    }

    // 4) Output projection (cp.async tf32 mma)
    {
        dim3 grid(Dn / 128, NROWS / 128);
        mma_gemm_ca<<<grid, 256, GEMM2_SMEM>>>(y, wo, out_b, out,
                                               NROWS, Dn, Dn);
    }
}